// round 8
// baseline (speedup 1.0000x reference)
#include <cuda_runtime.h>

// noiseRNN: h_t = tanh(W_ih x_t + b_ih + W_hh h_{t-1} + b_hh); carry h_t + 0.1*noise_t
// T=2048, B=256, I=64, H=128.
// 256 blocks x 256 threads (1 batch/block, 2 CTAs/SM). Thread (j = tid>>1,
// half = tid&1) owns output row j and K-half [96*half, 96*half+96) in registers
// (48 packed f32x2). Halves combined with one shfl_xor. z double-buffered
// (1 barrier/step) and stored twice (copy1 at +208 words) so the two per-warp
// broadcast groups hit disjoint bank sets.

#define T_STEPS 2048
#define BATCH   256
#define IN_DIM  64
#define HID     128
#define KDIM    192
#define STD_F   0.1f

// z buffer layout (in floats): copy0 at [0,192), copy1 at [208, 400), stride 416
#define ZCOPY1  208
#define ZSTRIDE 416

__device__ __forceinline__ unsigned long long fma2(unsigned long long a,
                                                   unsigned long long b,
                                                   unsigned long long c) {
    unsigned long long d;
    asm("fma.rn.f32x2 %0, %1, %2, %3;" : "=l"(d) : "l"(a), "l"(b), "l"(c));
    return d;
}
__device__ __forceinline__ unsigned long long packf2(float lo, float hi) {
    return (unsigned long long)__float_as_uint(lo) |
           ((unsigned long long)__float_as_uint(hi) << 32);
}
__device__ __forceinline__ float lo_f(unsigned long long v) {
    return __uint_as_float((unsigned)v);
}
__device__ __forceinline__ float hi_f(unsigned long long v) {
    return __uint_as_float((unsigned)(v >> 32));
}
// tanh(s) = 1 - 2/(exp(2s)+1): 2 MUFU + 4 fp ops, ~1e-6 accuracy.
__device__ __forceinline__ float fast_tanh(float s) {
    float e = __expf(2.0f * s);
    return 1.0f - __fdividef(2.0f, e + 1.0f);
}

__global__ void __launch_bounds__(256, 2) noise_rnn_kernel(
    const float* __restrict__ x,         // [T,B,I]
    const float* __restrict__ w_ih,      // [H,I]
    const float* __restrict__ w_hh,      // [H,H]
    const float* __restrict__ b_ih,      // [H]
    const float* __restrict__ b_hh,      // [H]
    const float* __restrict__ noise,     // [T,B,H]
    const float* __restrict__ hidden_in, // [1,B,H]
    float* __restrict__ out,             // [T,B,H] (+ [1,B,H] h_last)
    int out_size)
{
    __shared__ __align__(16) float zs[2 * ZSTRIDE];   // double-buffered, dual-copy

    const int tid  = threadIdx.x;
    const int j    = tid >> 1;      // output row 0..127
    const int half = tid & 1;       // K-half: 0 -> k in [0,96), 1 -> [96,192)
    const int b    = blockIdx.x;    // batch

    // --- weight half-row in registers, k-pair packed ---
    // W_cat[j][k] = k < HID ? w_hh[j][k] : w_ih[j][k-HID]
    unsigned long long wpk[48];
    {
        const int kbase = half * 96;
        const float* whr = w_hh + j * HID;
        const float* wir = w_ih + j * IN_DIM;
#pragma unroll
        for (int p = 0; p < 48; ++p) {
            const int k0 = kbase + 2 * p;
            const float lo = (k0 < HID)     ? whr[k0]       : wir[k0 - HID];
            const float hi = (k0 + 1 < HID) ? whr[k0 + 1]   : wir[k0 + 1 - HID];
            wpk[p] = packf2(lo, hi);
        }
    }

    const float bias = b_ih[j] + b_hh[j];
    const bool  isEven = (half == 0);
    const bool  isXst  = (!isEven) && (j < IN_DIM);   // odd threads stage x

    // --- init buffer 0: z = [h0; x0], both copies ---
    if (isEven) {
        const float h0 = hidden_in[b * HID + j];
        zs[j] = h0;
        zs[ZCOPY1 + j] = h0;
    }
    if (isXst) {
        const float x0 = x[b * IN_DIM + j];
        zs[HID + j] = x0;
        zs[ZCOPY1 + HID + j] = x0;
    }
    __syncthreads();

    const int nb = b * HID + j;       // noise/out per-step offset (even threads)
    const int xb = b * IN_DIM + j;    // x per-step offset (odd, j<64)

    // read base: half0 reads copy0 words [0,96); half1 reads copy1 words [304,400)
    const int rdoff = half ? (ZCOPY1 + 96) : 0;

    for (int t = 0; t < T_STEPS; ++t) {
        const int cur = (t & 1) * ZSTRIDE;
        const int nxt = ((t + 1) & 1) * ZSTRIDE;

        // prefetch (consumed after the matvec)
        const float nz = isEven ? noise[t * (BATCH * HID) + nb] : 0.0f;
        const bool ldx = isXst && (t + 1 < T_STEPS);
        float xn = 0.0f;
        if (ldx) xn = x[(t + 1) * (BATCH * IN_DIM) + xb];

        // --- half-K dot product: 24 LDS.128 + 48 fma2, 4 chains ---
        unsigned long long a0 = 0ull, a1 = 0ull, a2 = 0ull, a3 = 0ull;
        const ulonglong2* zq = reinterpret_cast<const ulonglong2*>(zs + cur + rdoff);
#pragma unroll
        for (int i = 0; i < 24; ++i) {
            const ulonglong2 v = zq[i];     // per-half broadcast, conflict-free
            if (i & 1) {
                a1 = fma2(wpk[2 * i],     v.x, a1);
                a3 = fma2(wpk[2 * i + 1], v.y, a3);
            } else {
                a0 = fma2(wpk[2 * i],     v.x, a0);
                a2 = fma2(wpk[2 * i + 1], v.y, a2);
            }
        }
        const float sh = ((lo_f(a0) + hi_f(a0)) + (lo_f(a1) + hi_f(a1)))
                       + ((lo_f(a2) + hi_f(a2)) + (lo_f(a3) + hi_f(a3)));
        const float s = sh + __shfl_xor_sync(0xFFFFFFFFu, sh, 1) + bias;

        if (isEven) {
            const float hn = fast_tanh(s);
            out[t * (BATCH * HID) + nb] = hn;
            const float zn = hn + STD_F * nz;       // noisy carried state
            zs[nxt + j] = zn;                       // next buffer, both copies
            zs[nxt + ZCOPY1 + j] = zn;
            if (t == T_STEPS - 1 && out_size > T_STEPS * BATCH * HID)
                out[T_STEPS * (BATCH * HID) + nb] = zn;   // h_last
        }
        if (ldx) {
            zs[nxt + HID + j] = xn;                 // stage next x, both copies
            zs[nxt + ZCOPY1 + HID + j] = xn;
        }
        __syncthreads();   // single barrier: next-buf writes visible; cur reads done
    }
}

extern "C" void kernel_launch(void* const* d_in, const int* in_sizes, int n_in,
                              void* d_out, int out_size) {
    const float* x         = (const float*)d_in[0];
    const float* w_ih      = (const float*)d_in[1];
    const float* w_hh      = (const float*)d_in[2];
    const float* b_ih      = (const float*)d_in[3];
    const float* b_hh      = (const float*)d_in[4];
    const float* noise     = (const float*)d_in[5];
    const float* hidden_in = (const float*)d_in[6];
    float* out = (float*)d_out;

    noise_rnn_kernel<<<BATCH, 256>>>(x, w_ih, w_hh, b_ih, b_hh,
                                     noise, hidden_in, out, out_size);
}

// round 10
// speedup vs baseline: 1.7558x; 1.7558x over previous
#include <cuda_runtime.h>

// noiseRNN: h_t = tanh(W_ih x_t + b_ih + W_hh h_{t-1} + b_hh); carry h_t + 0.1*noise_t
// T=2048, B=256, I=64, H=128. R3 structure (measured best): 128 blocks x 2 batches,
// 256 threads, W in registers (4j x 24k per thread), f32x2 FMAs, SMEM partial reduce.
// R9 fixes: depth-4 register prefetch pipeline for noise/x (kills per-step DRAM
// latency exposure), fast tanh, bias in register. (Resubmission: R9 bench was an
// infra failure, kernel never ran.)

#define T_STEPS 2048
#define BATCH   256
#define IN_DIM  64
#define HID     128
#define KDIM    192           // HID + IN_DIM
#define STD_F   0.1f

#define NWARPS  8
#define KSLICE  24            // KDIM / NWARPS
#define THREADS 256
#define NP      4             // prefetch pipeline depth (T_STEPS % NP == 0)

__device__ __forceinline__ unsigned long long fma2(unsigned long long a,
                                                   unsigned long long b,
                                                   unsigned long long c) {
    unsigned long long d;
    asm("fma.rn.f32x2 %0, %1, %2, %3;" : "=l"(d) : "l"(a), "l"(b), "l"(c));
    return d;
}
__device__ __forceinline__ unsigned long long packf2(float lo, float hi) {
    return (unsigned long long)__float_as_uint(lo) |
           ((unsigned long long)__float_as_uint(hi) << 32);
}
__device__ __forceinline__ float lo_f(unsigned long long v) {
    return __uint_as_float((unsigned)v);
}
__device__ __forceinline__ float hi_f(unsigned long long v) {
    return __uint_as_float((unsigned)(v >> 32));
}
// tanh(s) = 1 - 2/(exp(2s)+1): 2 MUFU + 4 fp ops, ~1e-6 accuracy (validated R5-R8).
__device__ __forceinline__ float fast_tanh(float s) {
    float e = __expf(2.0f * s);
    return 1.0f - __fdividef(2.0f, e + 1.0f);
}

__global__ void __launch_bounds__(THREADS, 1) noise_rnn_kernel(
    const float* __restrict__ x,         // [T,B,I]
    const float* __restrict__ w_ih,      // [H,I]
    const float* __restrict__ w_hh,      // [H,H]
    const float* __restrict__ b_ih,      // [H]
    const float* __restrict__ b_hh,      // [H]
    const float* __restrict__ noise,     // [T,B,H]
    const float* __restrict__ hidden_in, // [1,B,H]
    float* __restrict__ out,             // [T,B,H] (+ [1,B,H] h_last)
    int out_size)
{
    __shared__ __align__(16) float zA[KDIM];
    __shared__ __align__(16) float zB[KDIM];
    __shared__ __align__(16) float psh[NWARPS * 256];   // [warp][j*2 + b]

    const int tid   = threadIdx.x;
    const int lane  = tid & 31;
    const int warp  = tid >> 5;
    const int b0    = blockIdx.x * 2;
    const int jbase = lane * 4;        // this thread's 4 output rows
    const int ks    = warp * KSLICE;   // this thread's k-slice start

    // reduction role: thread tid handles output (j = tid>>1, b = tid&1)
    const int rj = tid >> 1;
    const int rb = tid & 1;
    const int gb = b0 + rb;            // global batch index for reduction role

    // --- W_cat tile in registers, k-pair packed ---
    // W_cat[j][k] = k < HID ? w_hh[j][k] : w_ih[j][k-HID]
    unsigned long long wpk[4][12];
#pragma unroll
    for (int p = 0; p < 12; ++p) {
        const int k0 = ks + 2 * p;
        const int k1 = k0 + 1;
#pragma unroll
        for (int jj = 0; jj < 4; ++jj) {
            const int j = jbase + jj;
            const float lo = (k0 < HID) ? w_hh[j * HID + k0]
                                        : w_ih[j * IN_DIM + (k0 - HID)];
            const float hi = (k1 < HID) ? w_hh[j * HID + k1]
                                        : w_ih[j * IN_DIM + (k1 - HID)];
            wpk[jj][p] = packf2(lo, hi);
        }
    }

    const float bias_r = b_ih[rj] + b_hh[rj];
    const bool  isXth  = (tid < 2 * IN_DIM);   // threads that stage x (rj < 64)

    // --- init z(t=0) ---
    {
        float* zp = rb ? zB : zA;
        zp[rj] = hidden_in[gb * HID + rj];           // h0
        if (isXth) zp[HID + rj] = x[gb * IN_DIM + rj];   // x[0]
    }
    __syncthreads();

    const int noise_base = gb * HID + rj;
    const int x_base     = gb * IN_DIM + rj;

    // --- depth-NP prefetch pipeline: nzbuf[u] = noise[t], xbuf[u] = x[t+1] ---
    float nzbuf[NP], xbuf[NP];
#pragma unroll
    for (int u = 0; u < NP; ++u) {
        nzbuf[u] = noise[u * (BATCH * HID) + noise_base];
        xbuf[u]  = (isXth && (u + 1) < T_STEPS)
                   ? x[(u + 1) * (BATCH * IN_DIM) + x_base] : 0.0f;
    }

    for (int t = 0; t < T_STEPS; t += NP) {
#pragma unroll
        for (int u = 0; u < NP; ++u) {
            const int tt = t + u;

            // consume pipelined values, refill for step tt+NP (in flight ~NP steps)
            const float nz = nzbuf[u];
            const float xn = xbuf[u];
            if (tt + NP < T_STEPS)
                nzbuf[u] = noise[(tt + NP) * (BATCH * HID) + noise_base];
            if (isXth && (tt + NP + 1) < T_STEPS)
                xbuf[u] = x[(tt + NP + 1) * (BATCH * IN_DIM) + x_base];

            // --- matvec partials: 4 j-rows x 24 k x 2 batches ---
            unsigned long long accA[4] = {0ull, 0ull, 0ull, 0ull};
            unsigned long long accB[4] = {0ull, 0ull, 0ull, 0ull};
            const ulonglong2* zAp = reinterpret_cast<const ulonglong2*>(zA + ks);
            const ulonglong2* zBp = reinterpret_cast<const ulonglong2*>(zB + ks);
#pragma unroll
            for (int q = 0; q < 6; ++q) {
                const ulonglong2 va = zAp[q];   // warp-uniform broadcast LDS.128
                const ulonglong2 vb = zBp[q];
#pragma unroll
                for (int jj = 0; jj < 4; ++jj) {
                    accA[jj] = fma2(wpk[jj][2 * q],     va.x, accA[jj]);
                    accA[jj] = fma2(wpk[jj][2 * q + 1], va.y, accA[jj]);
                    accB[jj] = fma2(wpk[jj][2 * q],     vb.x, accB[jj]);
                    accB[jj] = fma2(wpk[jj][2 * q + 1], vb.y, accB[jj]);
                }
            }

            // --- store partials (horizontal add of the f32x2 halves) ---
            {
                float4 p0, p1;
                p0.x = lo_f(accA[0]) + hi_f(accA[0]);
                p0.y = lo_f(accB[0]) + hi_f(accB[0]);
                p0.z = lo_f(accA[1]) + hi_f(accA[1]);
                p0.w = lo_f(accB[1]) + hi_f(accB[1]);
                p1.x = lo_f(accA[2]) + hi_f(accA[2]);
                p1.y = lo_f(accB[2]) + hi_f(accB[2]);
                p1.z = lo_f(accA[3]) + hi_f(accA[3]);
                p1.w = lo_f(accB[3]) + hi_f(accB[3]);
                float4* pp = reinterpret_cast<float4*>(psh + warp * 256 + jbase * 2);
                pp[0] = p0;
                pp[1] = p1;
            }
            __syncthreads();

            // --- reduce: thread tid owns output (rj, rb); psh index j*2+b == tid ---
            const float q0 = psh[0 * 256 + tid];
            const float q1 = psh[1 * 256 + tid];
            const float q2 = psh[2 * 256 + tid];
            const float q3 = psh[3 * 256 + tid];
            const float q4 = psh[4 * 256 + tid];
            const float q5 = psh[5 * 256 + tid];
            const float q6 = psh[6 * 256 + tid];
            const float q7 = psh[7 * 256 + tid];
            const float s = (((q0 + q1) + (q2 + q3)) + ((q4 + q5) + (q6 + q7)))
                          + bias_r;

            const float hn = fast_tanh(s);
            out[tt * (BATCH * HID) + noise_base] = hn;

            const float zn = hn + STD_F * nz;       // noisy carried state
            float* zp = rb ? zB : zA;
            zp[rj] = zn;
            if (isXth && (tt + 1) < T_STEPS)
                zp[HID + rj] = xn;                  // stage next x into z

            if (tt == T_STEPS - 1 && out_size > T_STEPS * BATCH * HID)
                out[T_STEPS * (BATCH * HID) + noise_base] = zn;   // h_last

            __syncthreads();
        }
    }
}

extern "C" void kernel_launch(void* const* d_in, const int* in_sizes, int n_in,
                              void* d_out, int out_size) {
    const float* x         = (const float*)d_in[0];
    const float* w_ih      = (const float*)d_in[1];
    const float* w_hh      = (const float*)d_in[2];
    const float* b_ih      = (const float*)d_in[3];
    const float* b_hh      = (const float*)d_in[4];
    const float* noise     = (const float*)d_in[5];
    const float* hidden_in = (const float*)d_in[6];
    float* out = (float*)d_out;

    noise_rnn_kernel<<<BATCH / 2, THREADS>>>(x, w_ih, w_hh, b_ih, b_hh,
                                             noise, hidden_in, out, out_size);
}